// round 15
// baseline (speedup 1.0000x reference)
#include <cuda_runtime.h>
#include <cuda_bf16.h>
#include <math_constants.h>
#include <cstdint>

// Problem constants
#define BQ 1024
#define DD 512
#define NN 131072
#define KK 16
#define NCAND 32
#define NTILES (NN / 128)       // 1024 n-tiles
#define PPT 8                   // partial entries per (query, tile)

// ---------------------------------------------------------------------------
// Helpers
// ---------------------------------------------------------------------------
__device__ __forceinline__ uint32_t smem_u32(const void* p) {
    uint32_t a;
    asm("{ .reg .u64 t; cvta.to.shared.u64 t, %1; cvt.u32.u64 %0, t; }" : "=r"(a) : "l"(p));
    return a;
}
__device__ __forceinline__ uint32_t sw128(uint32_t o) { return o ^ ((o >> 3) & 0x70); }

#define CP_ASYNC16(smem_addr, gptr) \
    asm volatile("cp.async.cg.shared.global [%0], [%1], 16;" :: "r"(smem_addr), "l"(gptr))
#define CP_COMMIT() asm volatile("cp.async.commit_group;")
#define CP_WAIT(N)  asm volatile("cp.async.wait_group %0;" :: "n"(N))

#define LDMATRIX_X4(r0, r1, r2, r3, addr) \
    asm volatile("ldmatrix.sync.aligned.m8n8.x4.shared.b16 {%0,%1,%2,%3}, [%4];" \
        : "=r"(r0), "=r"(r1), "=r"(r2), "=r"(r3) : "r"(addr))

#define MMA_BF16(c, a, b) \
    asm volatile("mma.sync.aligned.m16n8k16.row.col.f32.bf16.bf16.f32 " \
        "{%0,%1,%2,%3}, {%4,%5,%6,%7}, {%8,%9}, {%0,%1,%2,%3};" \
        : "+f"((c)[0]), "+f"((c)[1]), "+f"((c)[2]), "+f"((c)[3]) \
        : "r"((a)[0]), "r"((a)[1]), "r"((a)[2]), "r"((a)[3]), "r"((b)[0]), "r"((b)[1]))

// ---------------------------------------------------------------------------
// Scratch
// ---------------------------------------------------------------------------
__device__ float          g_qn[BQ * DD];
__device__ __nv_bfloat16  g_qnb[BQ * DD];
__device__ float          g_wt[(size_t)NN * DD];
__device__ __nv_bfloat16  g_wtb[(size_t)NN * DD];
__device__ float          g_pv[(size_t)BQ * NTILES * PPT];
__device__ int            g_pi[(size_t)BQ * NTILES * PPT];
__device__ int            g_cand[BQ * NCAND];

// ---------------------------------------------------------------------------
// Kernel 1: normalize queries -> fp32 + bf16 (main stream, before GEMM)
// ---------------------------------------------------------------------------
__global__ __launch_bounds__(128) void normalize_kernel(const float* __restrict__ q) {
    int row = blockIdx.x;
    const float* src = q + (size_t)row * DD;
    float v[4];
    float s = 0.f;
#pragma unroll
    for (int i = 0; i < 4; i++) { v[i] = src[threadIdx.x + i * 128]; s += v[i] * v[i]; }
#pragma unroll
    for (int o = 16; o > 0; o >>= 1) s += __shfl_xor_sync(0xffffffffu, s, o);
    __shared__ float red[4];
    if ((threadIdx.x & 31) == 0) red[threadIdx.x >> 5] = s;
    __syncthreads();
    float inv = rsqrtf(red[0] + red[1] + red[2] + red[3]);
#pragma unroll
    for (int i = 0; i < 4; i++) {
        float f = v[i] * inv;
        int d = threadIdx.x + i * 128;
        g_qn[(size_t)row * DD + d]  = f;
        g_qnb[(size_t)row * DD + d] = __float2bfloat16(f);
    }
}

// ---------------------------------------------------------------------------
// Kernel 2a: transpose W[D,N] -> g_wtb[N,D] bf16 only (CRITICAL PATH for GEMM)
// ---------------------------------------------------------------------------
#define TP 65   // smem pitch (floats)

__global__ __launch_bounds__(256) void transpose_b16_kernel(const float* __restrict__ W) {
    __shared__ float tile[64 * TP];
    const int bx = blockIdx.x;
    const int by = blockIdx.y;
    const int t  = threadIdx.x;

    {
        const int r = t >> 2, s = t & 3;
        const float* src = W + (size_t)(by * 64 + r) * NN + bx * 64 + s * 16;
#pragma unroll
        for (int j = 0; j < 4; j++) {
            float4 v = *(const float4*)(src + j * 4);
            float* dst = &tile[r * TP + s * 16 + j * 4];
            dst[0] = v.x; dst[1] = v.y; dst[2] = v.z; dst[3] = v.w;
        }
    }
    __syncthreads();

    {
        const int nr = t >> 2, s = t & 3;
        const int n = bx * 64 + nr;
        const int d0 = by * 64 + s * 16;
        float vals[16];
#pragma unroll
        for (int j = 0; j < 16; j++)
            vals[j] = tile[(s * 16 + j) * TP + nr];

        uint32_t pk[8];
#pragma unroll
        for (int j = 0; j < 8; j++) {
            __nv_bfloat162 b2 = __float22bfloat162_rn(make_float2(vals[2*j], vals[2*j+1]));
            pk[j] = *(uint32_t*)&b2;
        }
        uint4* dst16 = (uint4*)(g_wtb + (size_t)n * DD + d0);
        dst16[0] = make_uint4(pk[0], pk[1], pk[2], pk[3]);
        dst16[1] = make_uint4(pk[4], pk[5], pk[6], pk[7]);
    }
}

// ---------------------------------------------------------------------------
// Kernel 2b: transpose W[D,N] -> g_wt[N,D] fp32 (side stream; starts AFTER the
// bf16 transpose, overlaps the GEMM's ~490us compute shadow; feeds refine only)
// ---------------------------------------------------------------------------
__global__ __launch_bounds__(256) void transpose_f32_kernel(const float* __restrict__ W) {
    __shared__ float tile[64 * TP];
    const int bx = blockIdx.x;
    const int by = blockIdx.y;
    const int t  = threadIdx.x;

    {
        const int r = t >> 2, s = t & 3;
        const float* src = W + (size_t)(by * 64 + r) * NN + bx * 64 + s * 16;
#pragma unroll
        for (int j = 0; j < 4; j++) {
            float4 v = *(const float4*)(src + j * 4);
            float* dst = &tile[r * TP + s * 16 + j * 4];
            dst[0] = v.x; dst[1] = v.y; dst[2] = v.z; dst[3] = v.w;
        }
    }
    __syncthreads();

    {
        const int nr = t >> 2, s = t & 3;
        const int n = bx * 64 + nr;
        const int d0 = by * 64 + s * 16;
        float* dst32 = g_wt + (size_t)n * DD + d0;
#pragma unroll
        for (int j = 0; j < 4; j++) {
            float4 v;
            v.x = tile[(s * 16 + j * 4 + 0) * TP + nr];
            v.y = tile[(s * 16 + j * 4 + 1) * TP + nr];
            v.z = tile[(s * 16 + j * 4 + 2) * TP + nr];
            v.w = tile[(s * 16 + j * 4 + 3) * TP + nr];
            *(float4*)(dst32 + j * 4) = v;
        }
    }
}

// ---------------------------------------------------------------------------
// Kernel 3: bf16 HMMA GEMM, 4 warps x 64x64 warp tiles (round-12 winner).
// ---------------------------------------------------------------------------
#define BKG 64
#define STG_BYTES 16384
#define AOFFS(s) ((uint32_t)((s) * STG_BYTES))
#define BOFFS(s) ((uint32_t)(49152 + (s) * STG_BYTES))
#define SMEM_TOTAL 98304

__global__ __launch_bounds__(128, 2) void gemm_kernel() {
    extern __shared__ char smem[];
    const uint32_t sb = smem_u32(smem);
    const int tid = threadIdx.x, wid = tid >> 5, lane = tid & 31;
    const int q0 = blockIdx.x * 128;
    const int nb = blockIdx.y * 128;

    const int ldrow = tid >> 3;
    const int ldseg = tid & 7;

    auto issue = [&](int kc, int stg) {
        const __nv_bfloat16* As = g_qnb + (size_t)q0 * DD + kc * BKG;
        const __nv_bfloat16* Bs = g_wtb + (size_t)nb * DD + kc * BKG;
#pragma unroll
        for (int i = 0; i < 8; i++) {
            int row = ldrow + i * 16;
            uint32_t off = sw128((uint32_t)(row * 128 + ldseg * 16));
            CP_ASYNC16(sb + AOFFS(stg) + off, As + (size_t)row * DD + ldseg * 8);
            CP_ASYNC16(sb + BOFFS(stg) + off, Bs + (size_t)row * DD + ldseg * 8);
        }
        CP_COMMIT();
    };

    float c[4][8][4];
#pragma unroll
    for (int mi = 0; mi < 4; mi++)
#pragma unroll
        for (int ni = 0; ni < 8; ni++)
#pragma unroll
            for (int r = 0; r < 4; r++) c[mi][ni][r] = 0.f;

    const int wm = (wid >> 1) * 64;
    const int wn = (wid & 1) * 64;
    const int lrow = lane & 15;
    const int lkh  = lane >> 4;

    issue(0, 0);
    issue(1, 1);

#pragma unroll 1
    for (int kc = 0; kc < 8; kc++) {
        const int stg = kc % 3;
        if (kc == 7) { CP_WAIT(0); } else { CP_WAIT(1); }
        __syncthreads();
        if (kc + 2 < 8) issue(kc + 2, (kc + 2) % 3);

        const uint32_t ab = sb + AOFFS(stg);
        const uint32_t bb = sb + BOFFS(stg);
#pragma unroll
        for (int ks = 0; ks < 4; ks++) {
            const int k0 = ks * 16;
            uint32_t a[4][4];
#pragma unroll
            for (int mi = 0; mi < 4; mi++) {
                uint32_t addr = ab + sw128((uint32_t)((wm + mi * 16 + lrow) * 128 + (k0 + lkh * 8) * 2));
                LDMATRIX_X4(a[mi][0], a[mi][1], a[mi][2], a[mi][3], addr);
            }
            uint32_t b[8][2];
#pragma unroll
            for (int nj = 0; nj < 4; nj++) {
                uint32_t r0, r1, r2, r3;
                uint32_t addr = bb + sw128((uint32_t)((wn + nj * 16 + lrow) * 128 + (k0 + lkh * 8) * 2));
                LDMATRIX_X4(r0, r1, r2, r3, addr);
                b[2 * nj][0] = r0; b[2 * nj + 1][0] = r1;
                b[2 * nj][1] = r2; b[2 * nj + 1][1] = r3;
            }
#pragma unroll
            for (int mi = 0; mi < 4; mi++)
#pragma unroll
                for (int ni = 0; ni < 8; ni++)
                    MMA_BF16(c[mi][ni], a[mi], b[ni]);
        }
        __syncthreads();
    }

    // ---- stage C tile (128x128 bf16) in smem ----
    const int crow = lane >> 2;
    const int ccol2 = (lane & 3) * 2;
#pragma unroll
    for (int mi = 0; mi < 4; mi++)
#pragma unroll
        for (int ni = 0; ni < 8; ni++) {
            int m = wm + mi * 16 + crow;
            int n = wn + ni * 8 + ccol2;
            __nv_bfloat162 p0 = __float22bfloat162_rn(make_float2(c[mi][ni][0], c[mi][ni][1]));
            __nv_bfloat162 p1 = __float22bfloat162_rn(make_float2(c[mi][ni][2], c[mi][ni][3]));
            *(__nv_bfloat162*)(smem + m * 256 + n * 2)       = p0;
            *(__nv_bfloat162*)(smem + (m + 8) * 256 + n * 2) = p1;
        }
    __syncthreads();

    // ---- fused selection: 1 thread per query row, two 64-col halves ----
    {
        const int row = tid;
        const int rot = row & 31;
#pragma unroll
        for (int half = 0; half < 2; half++) {
            float v0 = -CUDART_INF_F, v1 = -CUDART_INF_F, v2 = -CUDART_INF_F, v3 = -CUDART_INF_F;
            int   i0 = 0x7fffffff, i1 = 0x7fffffff, i2 = 0x7fffffff, i3 = 0x7fffffff;
#pragma unroll
            for (int p = 0; p < 32; p++) {
                int pp = (p + rot) & 31;
                uint32_t w = *(uint32_t*)(smem + row * 256 + half * 128 + pp * 4);
                __nv_bfloat162 b2 = *(__nv_bfloat162*)&w;
                float x0 = __low2float(b2);
                float x1 = __high2float(b2);
                int   n0 = nb + half * 64 + pp * 2;
#pragma unroll
                for (int h = 0; h < 2; h++) {
                    float x = h ? x1 : x0;
                    int   n = n0 + h;
                    bool p0c = x > v0, p1c = x > v1, p2c = x > v2, p3c = x > v3;
                    v3 = p2c ? v2 : (p3c ? x : v3);  i3 = p2c ? i2 : (p3c ? n : i3);
                    v2 = p1c ? v1 : (p2c ? x : v2);  i2 = p1c ? i1 : (p2c ? n : i2);
                    v1 = p0c ? v0 : (p1c ? x : v1);  i1 = p0c ? i0 : (p1c ? n : i1);
                    v0 = p0c ? x  : v0;              i0 = p0c ? n : i0;
                }
            }
            size_t base = ((size_t)(q0 + row) * NTILES + blockIdx.y) * PPT + half * 4;
            *(float4*)(g_pv + base) = make_float4(v0, v1, v2, v3);
            *(int4*)  (g_pi + base) = make_int4(i0, i1, i2, i3);
        }
    }
}

// ---------------------------------------------------------------------------
// Kernel 4: per-query top-32 from the 8192 partials (round-6/12 version)
// ---------------------------------------------------------------------------
#define TL 8
__global__ __launch_bounds__(256) void cand_kernel() {
    const int q = blockIdx.x;
    const int tid = threadIdx.x;
    const float* pv = g_pv + (size_t)q * NTILES * PPT;
    const int*   pi = g_pi + (size_t)q * NTILES * PPT;

    float tv[TL]; int ti[TL];
#pragma unroll
    for (int i = 0; i < TL; i++) { tv[i] = -CUDART_INF_F; ti[i] = 0x7fffffff; }

#pragma unroll
    for (int b = 0; b < 8; b++) {
        float4 v = *(const float4*)(pv + tid * 32 + b * 4);
        int4   x = *(const int4*)(pi + tid * 32 + b * 4);
        float xs[4] = {v.x, v.y, v.z, v.w};
        int   ns[4] = {x.x, x.y, x.z, x.w};
#pragma unroll
        for (int e = 0; e < 4; e++) {
            float xx = xs[e]; int nn = ns[e];
            bool c0 = xx > tv[0], c1 = xx > tv[1], c2 = xx > tv[2], c3 = xx > tv[3];
            bool c4 = xx > tv[4], c5 = xx > tv[5], c6 = xx > tv[6], c7 = xx > tv[7];
            tv[7] = c6 ? tv[6] : (c7 ? xx : tv[7]);  ti[7] = c6 ? ti[6] : (c7 ? nn : ti[7]);
            tv[6] = c5 ? tv[5] : (c6 ? xx : tv[6]);  ti[6] = c5 ? ti[5] : (c6 ? nn : ti[6]);
            tv[5] = c4 ? tv[4] : (c5 ? xx : tv[5]);  ti[5] = c4 ? ti[4] : (c5 ? nn : ti[5]);
            tv[4] = c3 ? tv[3] : (c4 ? xx : tv[4]);  ti[4] = c3 ? ti[3] : (c4 ? nn : ti[4]);
            tv[3] = c2 ? tv[2] : (c3 ? xx : tv[3]);  ti[3] = c2 ? ti[2] : (c3 ? nn : ti[3]);
            tv[2] = c1 ? tv[1] : (c2 ? xx : tv[2]);  ti[2] = c1 ? ti[1] : (c2 ? nn : ti[2]);
            tv[1] = c0 ? tv[0] : (c1 ? xx : tv[1]);  ti[1] = c0 ? ti[0] : (c1 ? nn : ti[1]);
            tv[0] = c0 ? xx : tv[0];                 ti[0] = c0 ? nn : ti[0];
        }
    }

    __shared__ float sv[256 * TL];
    __shared__ int   si[256 * TL];
#pragma unroll
    for (int i = 0; i < TL; i++) {
        sv[tid * TL + i] = tv[i];
        si[tid * TL + i] = ti[i];
    }
    __syncthreads();

    if (tid < 32) {
        const int l = tid;
        float hv[8]; int hx[8]; int hp[8];
#pragma unroll
        for (int s = 0; s < 8; s++) {
            int t = l * 8 + s;
            hv[s] = sv[t * TL]; hx[s] = si[t * TL]; hp[s] = 0;
        }
#pragma unroll 1
        for (int sel = 0; sel < NCAND; sel++) {
            float bv = -CUDART_INF_F; int bi = 0x7fffffff; int bs = 0;
#pragma unroll
            for (int s = 0; s < 8; s++)
                if (hv[s] > bv || (hv[s] == bv && hx[s] < bi)) { bv = hv[s]; bi = hx[s]; bs = s; }
            float wv = bv; int wi = bi; int wl = l;
#pragma unroll
            for (int off = 16; off > 0; off >>= 1) {
                float ov = __shfl_xor_sync(0xffffffffu, wv, off);
                int   oi = __shfl_xor_sync(0xffffffffu, wi, off);
                int   ol = __shfl_xor_sync(0xffffffffu, wl, off);
                if (ov > wv || (ov == wv && oi < wi)) { wv = ov; wi = oi; wl = ol; }
            }
            if (l == wl) {
                g_cand[q * NCAND + sel] = wi;
                int t = l * 8 + bs;
                hp[bs]++;
                if (hp[bs] < TL) { hv[bs] = sv[t * TL + hp[bs]]; hx[bs] = si[t * TL + hp[bs]]; }
                else             { hv[bs] = -CUDART_INF_F;      hx[bs] = 0x7fffffff; }
            }
        }
    }
}

// ---------------------------------------------------------------------------
// Kernel 5: sequential-fp32 rescore of 32 candidates, top-16, write outputs
// ---------------------------------------------------------------------------
#define CHUNK 128
#define CPITCH 129

__global__ __launch_bounds__(256) void refine_kernel(const float* __restrict__ label,
                                                     float* __restrict__ out_scores,
                                                     float* __restrict__ out_idx_f,
                                                     float* __restrict__ out_seqs,
                                                     float* __restrict__ out_labels) {
    const int q = blockIdx.x;
    const int tid = threadIdx.x;

    __shared__ float qn_s[DD];
    __shared__ float chunk[NCAND * CPITCH];
    __shared__ float cv[NCAND];
    __shared__ int   ci[NCAND];
    __shared__ int   sel_idx[KK];

    if (tid < NCAND) ci[tid] = g_cand[q * NCAND + tid];
    for (int d = tid; d < DD; d += 256) qn_s[d] = g_qn[(size_t)q * DD + d];
    __syncthreads();

    float acc = 0.f;
#pragma unroll 1
    for (int ch = 0; ch < DD / CHUNK; ch++) {
        for (int idx = tid; idx < NCAND * CHUNK; idx += 256) {
            int c = idx >> 7, d = idx & (CHUNK - 1);
            chunk[c * CPITCH + d] = g_wt[(size_t)ci[c] * DD + ch * CHUNK + d];
        }
        __syncthreads();
        if (tid < NCAND) {
#pragma unroll
            for (int d = 0; d < CHUNK; d++)
                acc = fmaf(chunk[tid * CPITCH + d], qn_s[ch * CHUNK + d], acc);
        }
        __syncthreads();
    }
    if (tid < NCAND) cv[tid] = acc;
    __syncthreads();

    if (tid == 0) {
        bool used[NCAND] = {};
        for (int r = 0; r < KK; r++) {
            float best = -CUDART_INF_F; int bj = -1; int bidx = 0x7fffffff;
            for (int j = 0; j < NCAND; j++) {
                if (used[j]) continue;
                if (cv[j] > best || (cv[j] == best && ci[j] < bidx)) {
                    best = cv[j]; bj = j; bidx = ci[j];
                }
            }
            used[bj] = true;
            sel_idx[r] = ci[bj];
            out_scores[q * KK + r] = best;
            out_idx_f [q * KK + r] = (float)ci[bj];
            out_labels[q * KK + r] = label[ci[bj]];
        }
    }
    __syncthreads();

#pragma unroll 1
    for (int r = 0; r < KK; r++) {
        const float* row = g_wt + (size_t)sel_idx[r] * DD;
        float* dst = out_seqs + ((size_t)q * KK + r) * DD;
        for (int d = tid; d < DD; d += 256) dst[d] = row[d];
    }
}

// ---------------------------------------------------------------------------
// Launcher — fixed topology:
//   main: normalize -> transpose_b16 -> [e_fork] -> gemm -> cand -> wait(e1) -> refine
//   side: wait(e_fork) -> transpose_f32 -> [e1]
// transpose_f32 runs entirely under the GEMM's compute shadow (DRAM 4.6% busy).
// ---------------------------------------------------------------------------
extern "C" void kernel_launch(void* const* d_in, const int* in_sizes, int n_in,
                              void* d_out, int out_size) {
    const float* queries = (const float*)d_in[0];
    const float* weight  = (const float*)d_in[1];
    const float* label   = (const float*)d_in[2];

    float* out = (float*)d_out;
    float* out_scores = out;
    float* out_idx_f  = out + BQ * KK;
    float* out_seqs   = out + 2 * BQ * KK;
    float* out_labels = out + 2 * BQ * KK + (size_t)BQ * KK * DD;

    static cudaStream_t s1 = nullptr;
    static cudaEvent_t  e0 = nullptr, e1 = nullptr;
    if (!s1) {   // created on the (uncaptured) correctness call; reused in capture
        cudaStreamCreateWithFlags(&s1, cudaStreamNonBlocking);
        cudaEventCreateWithFlags(&e0, cudaEventDisableTiming);
        cudaEventCreateWithFlags(&e1, cudaEventDisableTiming);
        cudaFuncSetAttribute(gemm_kernel, cudaFuncAttributeMaxDynamicSharedMemorySize, SMEM_TOTAL);
    }

    // main stream: everything the GEMM depends on, in order
    normalize_kernel<<<BQ, 128>>>(queries);
    transpose_b16_kernel<<<dim3(NN / 64, DD / 64), 256>>>(weight);
    cudaEventRecord(e0, 0);                 // fork point: after bf16 transpose
    cudaStreamWaitEvent(s1, e0, 0);

    // side stream: fp32 transpose (refine-only input) overlaps the GEMM
    transpose_f32_kernel<<<dim3(NN / 64, DD / 64), 256, 0, s1>>>(weight);
    cudaEventRecord(e1, s1);

    // main stream: critical path
    gemm_kernel<<<dim3(BQ / 128, NN / 128), 128, SMEM_TOTAL>>>();
    cand_kernel<<<BQ, 256>>>();
    cudaStreamWaitEvent(0, e1, 0);          // join before refine consumes g_wt
    refine_kernel<<<BQ, 256>>>(label, out_scores, out_idx_f, out_seqs, out_labels);
}

// round 16
// speedup vs baseline: 1.0657x; 1.0657x over previous
#include <cuda_runtime.h>
#include <cuda_bf16.h>
#include <math_constants.h>
#include <cstdint>

// Problem constants
#define BQ 1024
#define DD 512
#define NN 131072
#define KK 16
#define NCAND 32
#define NTILES (NN / 128)       // 1024 n-tiles
#define PPT 8                   // partial entries per (query, tile)

// ---------------------------------------------------------------------------
// Helpers
// ---------------------------------------------------------------------------
__device__ __forceinline__ uint32_t smem_u32(const void* p) {
    uint32_t a;
    asm("{ .reg .u64 t; cvta.to.shared.u64 t, %1; cvt.u32.u64 %0, t; }" : "=r"(a) : "l"(p));
    return a;
}
__device__ __forceinline__ uint32_t sw128(uint32_t o) { return o ^ ((o >> 3) & 0x70); }

#define CP_ASYNC16(smem_addr, gptr) \
    asm volatile("cp.async.cg.shared.global [%0], [%1], 16;" :: "r"(smem_addr), "l"(gptr))
#define CP_COMMIT() asm volatile("cp.async.commit_group;")
#define CP_WAIT(N)  asm volatile("cp.async.wait_group %0;" :: "n"(N))

#define LDMATRIX_X4(r0, r1, r2, r3, addr) \
    asm volatile("ldmatrix.sync.aligned.m8n8.x4.shared.b16 {%0,%1,%2,%3}, [%4];" \
        : "=r"(r0), "=r"(r1), "=r"(r2), "=r"(r3) : "r"(addr))

#define MMA_BF16(c, a, b) \
    asm volatile("mma.sync.aligned.m16n8k16.row.col.f32.bf16.bf16.f32 " \
        "{%0,%1,%2,%3}, {%4,%5,%6,%7}, {%8,%9}, {%0,%1,%2,%3};" \
        : "+f"((c)[0]), "+f"((c)[1]), "+f"((c)[2]), "+f"((c)[3]) \
        : "r"((a)[0]), "r"((a)[1]), "r"((a)[2]), "r"((a)[3]), "r"((b)[0]), "r"((b)[1]))

// ---------------------------------------------------------------------------
// Scratch
// ---------------------------------------------------------------------------
__device__ float          g_qn[BQ * DD];
__device__ __nv_bfloat16  g_qnb[BQ * DD];
__device__ float          g_wt[(size_t)NN * DD];
__device__ __nv_bfloat16  g_wtb[(size_t)NN * DD];
__device__ float          g_pv[(size_t)BQ * NTILES * PPT];
__device__ int            g_pi[(size_t)BQ * NTILES * PPT];
__device__ int            g_cand[BQ * NCAND];

// ---------------------------------------------------------------------------
// Kernel 1: normalize queries -> fp32 + bf16
// ---------------------------------------------------------------------------
__global__ __launch_bounds__(128) void normalize_kernel(const float* __restrict__ q) {
    int row = blockIdx.x;
    const float* src = q + (size_t)row * DD;
    float v[4];
    float s = 0.f;
#pragma unroll
    for (int i = 0; i < 4; i++) { v[i] = src[threadIdx.x + i * 128]; s += v[i] * v[i]; }
#pragma unroll
    for (int o = 16; o > 0; o >>= 1) s += __shfl_xor_sync(0xffffffffu, s, o);
    __shared__ float red[4];
    if ((threadIdx.x & 31) == 0) red[threadIdx.x >> 5] = s;
    __syncthreads();
    float inv = rsqrtf(red[0] + red[1] + red[2] + red[3]);
#pragma unroll
    for (int i = 0; i < 4; i++) {
        float f = v[i] * inv;
        int d = threadIdx.x + i * 128;
        g_qn[(size_t)row * DD + d]  = f;
        g_qnb[(size_t)row * DD + d] = __float2bfloat16(f);
    }
}

// ---------------------------------------------------------------------------
// Kernel 2: transpose W[D,N] -> W_t[N,D] fp32 + bf16 (round-12 version)
// ---------------------------------------------------------------------------
#define TP 65   // smem pitch (floats)

__global__ __launch_bounds__(256) void transpose_kernel(const float* __restrict__ W) {
    __shared__ float tile[64 * TP];
    const int bx = blockIdx.x;
    const int by = blockIdx.y;
    const int t  = threadIdx.x;

    {
        const int r = t >> 2, s = t & 3;
        const float* src = W + (size_t)(by * 64 + r) * NN + bx * 64 + s * 16;
#pragma unroll
        for (int j = 0; j < 4; j++) {
            float4 v = *(const float4*)(src + j * 4);
            float* dst = &tile[r * TP + s * 16 + j * 4];
            dst[0] = v.x; dst[1] = v.y; dst[2] = v.z; dst[3] = v.w;
        }
    }
    __syncthreads();

    {
        const int nr = t >> 2, s = t & 3;
        const int n = bx * 64 + nr;
        const int d0 = by * 64 + s * 16;
        float vals[16];
#pragma unroll
        for (int j = 0; j < 16; j++)
            vals[j] = tile[(s * 16 + j) * TP + nr];

        float* dst32 = g_wt + (size_t)n * DD + d0;
#pragma unroll
        for (int j = 0; j < 4; j++)
            *(float4*)(dst32 + j * 4) = make_float4(vals[4*j], vals[4*j+1], vals[4*j+2], vals[4*j+3]);

        uint32_t pk[8];
#pragma unroll
        for (int j = 0; j < 8; j++) {
            __nv_bfloat162 b2 = __float22bfloat162_rn(make_float2(vals[2*j], vals[2*j+1]));
            pk[j] = *(uint32_t*)&b2;
        }
        uint4* dst16 = (uint4*)(g_wtb + (size_t)n * DD + d0);
        dst16[0] = make_uint4(pk[0], pk[1], pk[2], pk[3]);
        dst16[1] = make_uint4(pk[4], pk[5], pk[6], pk[7]);
    }
}

// ---------------------------------------------------------------------------
// Kernel 3: bf16 HMMA GEMM, 4 warps x 64x64 warp tiles, with HOISTED swizzled
// LDSM addresses: sw128(row*128 + ks*32 + lkh*16) == sw128(row*128 + lkh*16)
// ^ (ks*32)  (swizzle mask is row-only; ks bits 5-6 add carry-free).
// Per address in the hot loop: 1 IADD (stage base) + 1 LOP3 (ks XOR).
// ---------------------------------------------------------------------------
#define BKG 64
#define STG_BYTES 16384
#define AOFFS(s) ((uint32_t)((s) * STG_BYTES))
#define BOFFS(s) ((uint32_t)(49152 + (s) * STG_BYTES))
#define SMEM_TOTAL 98304

__global__ __launch_bounds__(128, 2) void gemm_kernel() {
    extern __shared__ char smem[];
    const uint32_t sb = smem_u32(smem);
    const int tid = threadIdx.x, wid = tid >> 5, lane = tid & 31;
    const int q0 = blockIdx.x * 128;
    const int nb = blockIdx.y * 128;

    const int ldrow = tid >> 3;
    const int ldseg = tid & 7;

    auto issue = [&](int kc, int stg) {
        const __nv_bfloat16* As = g_qnb + (size_t)q0 * DD + kc * BKG;
        const __nv_bfloat16* Bs = g_wtb + (size_t)nb * DD + kc * BKG;
#pragma unroll
        for (int i = 0; i < 8; i++) {
            int row = ldrow + i * 16;
            uint32_t off = sw128((uint32_t)(row * 128 + ldseg * 16));
            CP_ASYNC16(sb + AOFFS(stg) + off, As + (size_t)row * DD + ldseg * 8);
            CP_ASYNC16(sb + BOFFS(stg) + off, Bs + (size_t)row * DD + ldseg * 8);
        }
        CP_COMMIT();
    };

    float c[4][8][4];
#pragma unroll
    for (int mi = 0; mi < 4; mi++)
#pragma unroll
        for (int ni = 0; ni < 8; ni++)
#pragma unroll
            for (int r = 0; r < 4; r++) c[mi][ni][r] = 0.f;

    const int wm = (wid >> 1) * 64;
    const int wn = (wid & 1) * 64;
    const int lrow = lane & 15;
    const int lkh  = lane >> 4;

    // hoisted swizzled base offsets (ks = 0), stage-independent
    uint32_t a_base[4], b_base[4];
#pragma unroll
    for (int mi = 0; mi < 4; mi++)
        a_base[mi] = sw128((uint32_t)((wm + mi * 16 + lrow) * 128 + lkh * 16));
#pragma unroll
    for (int nj = 0; nj < 4; nj++)
        b_base[nj] = sw128((uint32_t)((wn + nj * 16 + lrow) * 128 + lkh * 16));

    issue(0, 0);
    issue(1, 1);

#pragma unroll 1
    for (int kc = 0; kc < 8; kc++) {
        const int stg = kc % 3;
        if (kc == 7) { CP_WAIT(0); } else { CP_WAIT(1); }
        __syncthreads();
        if (kc + 2 < 8) issue(kc + 2, (kc + 2) % 3);

        const uint32_t ab = sb + AOFFS(stg);
        const uint32_t bb = sb + BOFFS(stg);
#pragma unroll
        for (int ks = 0; ks < 4; ks++) {
            const uint32_t kx = (uint32_t)(ks * 32);
            uint32_t a[4][4];
#pragma unroll
            for (int mi = 0; mi < 4; mi++) {
                uint32_t addr = ab + (a_base[mi] ^ kx);
                LDMATRIX_X4(a[mi][0], a[mi][1], a[mi][2], a[mi][3], addr);
            }
            uint32_t b[8][2];
#pragma unroll
            for (int nj = 0; nj < 4; nj++) {
                uint32_t r0, r1, r2, r3;
                uint32_t addr = bb + (b_base[nj] ^ kx);
                LDMATRIX_X4(r0, r1, r2, r3, addr);
                b[2 * nj][0] = r0; b[2 * nj + 1][0] = r1;
                b[2 * nj][1] = r2; b[2 * nj + 1][1] = r3;
            }
#pragma unroll
            for (int mi = 0; mi < 4; mi++)
#pragma unroll
                for (int ni = 0; ni < 8; ni++)
                    MMA_BF16(c[mi][ni], a[mi], b[ni]);
        }
        __syncthreads();
    }

    // ---- stage C tile (128x128 bf16) in smem ----
    const int crow = lane >> 2;
    const int ccol2 = (lane & 3) * 2;
#pragma unroll
    for (int mi = 0; mi < 4; mi++)
#pragma unroll
        for (int ni = 0; ni < 8; ni++) {
            int m = wm + mi * 16 + crow;
            int n = wn + ni * 8 + ccol2;
            __nv_bfloat162 p0 = __float22bfloat162_rn(make_float2(c[mi][ni][0], c[mi][ni][1]));
            __nv_bfloat162 p1 = __float22bfloat162_rn(make_float2(c[mi][ni][2], c[mi][ni][3]));
            *(__nv_bfloat162*)(smem + m * 256 + n * 2)       = p0;
            *(__nv_bfloat162*)(smem + (m + 8) * 256 + n * 2) = p1;
        }
    __syncthreads();

    // ---- fused selection: 1 thread per query row, two 64-col halves ----
    {
        const int row = tid;
        const int rot = row & 31;
#pragma unroll
        for (int half = 0; half < 2; half++) {
            float v0 = -CUDART_INF_F, v1 = -CUDART_INF_F, v2 = -CUDART_INF_F, v3 = -CUDART_INF_F;
            int   i0 = 0x7fffffff, i1 = 0x7fffffff, i2 = 0x7fffffff, i3 = 0x7fffffff;
#pragma unroll
            for (int p = 0; p < 32; p++) {
                int pp = (p + rot) & 31;
                uint32_t w = *(uint32_t*)(smem + row * 256 + half * 128 + pp * 4);
                __nv_bfloat162 b2 = *(__nv_bfloat162*)&w;
                float x0 = __low2float(b2);
                float x1 = __high2float(b2);
                int   n0 = nb + half * 64 + pp * 2;
#pragma unroll
                for (int h = 0; h < 2; h++) {
                    float x = h ? x1 : x0;
                    int   n = n0 + h;
                    bool p0c = x > v0, p1c = x > v1, p2c = x > v2, p3c = x > v3;
                    v3 = p2c ? v2 : (p3c ? x : v3);  i3 = p2c ? i2 : (p3c ? n : i3);
                    v2 = p1c ? v1 : (p2c ? x : v2);  i2 = p1c ? i1 : (p2c ? n : i2);
                    v1 = p0c ? v0 : (p1c ? x : v1);  i1 = p0c ? i0 : (p1c ? n : i1);
                    v0 = p0c ? x  : v0;              i0 = p0c ? n : i0;
                }
            }
            size_t base = ((size_t)(q0 + row) * NTILES + blockIdx.y) * PPT + half * 4;
            *(float4*)(g_pv + base) = make_float4(v0, v1, v2, v3);
            *(int4*)  (g_pi + base) = make_int4(i0, i1, i2, i3);
        }
    }
}

// ---------------------------------------------------------------------------
// Kernel 4: per-query top-32 from the 8192 partials (round-6/12 version)
// ---------------------------------------------------------------------------
#define TL 8
__global__ __launch_bounds__(256) void cand_kernel() {
    const int q = blockIdx.x;
    const int tid = threadIdx.x;
    const float* pv = g_pv + (size_t)q * NTILES * PPT;
    const int*   pi = g_pi + (size_t)q * NTILES * PPT;

    float tv[TL]; int ti[TL];
#pragma unroll
    for (int i = 0; i < TL; i++) { tv[i] = -CUDART_INF_F; ti[i] = 0x7fffffff; }

#pragma unroll
    for (int b = 0; b < 8; b++) {
        float4 v = *(const float4*)(pv + tid * 32 + b * 4);
        int4   x = *(const int4*)(pi + tid * 32 + b * 4);
        float xs[4] = {v.x, v.y, v.z, v.w};
        int   ns[4] = {x.x, x.y, x.z, x.w};
#pragma unroll
        for (int e = 0; e < 4; e++) {
            float xx = xs[e]; int nn = ns[e];
            bool c0 = xx > tv[0], c1 = xx > tv[1], c2 = xx > tv[2], c3 = xx > tv[3];
            bool c4 = xx > tv[4], c5 = xx > tv[5], c6 = xx > tv[6], c7 = xx > tv[7];
            tv[7] = c6 ? tv[6] : (c7 ? xx : tv[7]);  ti[7] = c6 ? ti[6] : (c7 ? nn : ti[7]);
            tv[6] = c5 ? tv[5] : (c6 ? xx : tv[6]);  ti[6] = c5 ? ti[5] : (c6 ? nn : ti[6]);
            tv[5] = c4 ? tv[4] : (c5 ? xx : tv[5]);  ti[5] = c4 ? ti[4] : (c5 ? nn : ti[5]);
            tv[4] = c3 ? tv[3] : (c4 ? xx : tv[4]);  ti[4] = c3 ? ti[3] : (c4 ? nn : ti[4]);
            tv[3] = c2 ? tv[2] : (c3 ? xx : tv[3]);  ti[3] = c2 ? ti[2] : (c3 ? nn : ti[3]);
            tv[2] = c1 ? tv[1] : (c2 ? xx : tv[2]);  ti[2] = c1 ? ti[1] : (c2 ? nn : ti[2]);
            tv[1] = c0 ? tv[0] : (c1 ? xx : tv[1]);  ti[1] = c0 ? ti[0] : (c1 ? nn : ti[1]);
            tv[0] = c0 ? xx : tv[0];                 ti[0] = c0 ? nn : ti[0];
        }
    }

    __shared__ float sv[256 * TL];
    __shared__ int   si[256 * TL];
#pragma unroll
    for (int i = 0; i < TL; i++) {
        sv[tid * TL + i] = tv[i];
        si[tid * TL + i] = ti[i];
    }
    __syncthreads();

    if (tid < 32) {
        const int l = tid;
        float hv[8]; int hx[8]; int hp[8];
#pragma unroll
        for (int s = 0; s < 8; s++) {
            int t = l * 8 + s;
            hv[s] = sv[t * TL]; hx[s] = si[t * TL]; hp[s] = 0;
        }
#pragma unroll 1
        for (int sel = 0; sel < NCAND; sel++) {
            float bv = -CUDART_INF_F; int bi = 0x7fffffff; int bs = 0;
#pragma unroll
            for (int s = 0; s < 8; s++)
                if (hv[s] > bv || (hv[s] == bv && hx[s] < bi)) { bv = hv[s]; bi = hx[s]; bs = s; }
            float wv = bv; int wi = bi; int wl = l;
#pragma unroll
            for (int off = 16; off > 0; off >>= 1) {
                float ov = __shfl_xor_sync(0xffffffffu, wv, off);
                int   oi = __shfl_xor_sync(0xffffffffu, wi, off);
                int   ol = __shfl_xor_sync(0xffffffffu, wl, off);
                if (ov > wv || (ov == wv && oi < wi)) { wv = ov; wi = oi; wl = ol; }
            }
            if (l == wl) {
                g_cand[q * NCAND + sel] = wi;
                int t = l * 8 + bs;
                hp[bs]++;
                if (hp[bs] < TL) { hv[bs] = sv[t * TL + hp[bs]]; hx[bs] = si[t * TL + hp[bs]]; }
                else             { hv[bs] = -CUDART_INF_F;      hx[bs] = 0x7fffffff; }
            }
        }
    }
}

// ---------------------------------------------------------------------------
// Kernel 5: sequential-fp32 rescore of 32 candidates, top-16, write outputs
// ---------------------------------------------------------------------------
#define CHUNK 128
#define CPITCH 129

__global__ __launch_bounds__(256) void refine_kernel(const float* __restrict__ label,
                                                     float* __restrict__ out_scores,
                                                     float* __restrict__ out_idx_f,
                                                     float* __restrict__ out_seqs,
                                                     float* __restrict__ out_labels) {
    const int q = blockIdx.x;
    const int tid = threadIdx.x;

    __shared__ float qn_s[DD];
    __shared__ float chunk[NCAND * CPITCH];
    __shared__ float cv[NCAND];
    __shared__ int   ci[NCAND];
    __shared__ int   sel_idx[KK];

    if (tid < NCAND) ci[tid] = g_cand[q * NCAND + tid];
    for (int d = tid; d < DD; d += 256) qn_s[d] = g_qn[(size_t)q * DD + d];
    __syncthreads();

    float acc = 0.f;
#pragma unroll 1
    for (int ch = 0; ch < DD / CHUNK; ch++) {
        for (int idx = tid; idx < NCAND * CHUNK; idx += 256) {
            int c = idx >> 7, d = idx & (CHUNK - 1);
            chunk[c * CPITCH + d] = g_wt[(size_t)ci[c] * DD + ch * CHUNK + d];
        }
        __syncthreads();
        if (tid < NCAND) {
#pragma unroll
            for (int d = 0; d < CHUNK; d++)
                acc = fmaf(chunk[tid * CPITCH + d], qn_s[ch * CHUNK + d], acc);
        }
        __syncthreads();
    }
    if (tid < NCAND) cv[tid] = acc;
    __syncthreads();

    if (tid == 0) {
        bool used[NCAND] = {};
        for (int r = 0; r < KK; r++) {
            float best = -CUDART_INF_F; int bj = -1; int bidx = 0x7fffffff;
            for (int j = 0; j < NCAND; j++) {
                if (used[j]) continue;
                if (cv[j] > best || (cv[j] == best && ci[j] < bidx)) {
                    best = cv[j]; bj = j; bidx = ci[j];
                }
            }
            used[bj] = true;
            sel_idx[r] = ci[bj];
            out_scores[q * KK + r] = best;
            out_idx_f [q * KK + r] = (float)ci[bj];
            out_labels[q * KK + r] = label[ci[bj]];
        }
    }
    __syncthreads();

#pragma unroll 1
    for (int r = 0; r < KK; r++) {
        const float* row = g_wt + (size_t)sel_idx[r] * DD;
        float* dst = out_seqs + ((size_t)q * KK + r) * DD;
        for (int d = tid; d < DD; d += 256) dst[d] = row[d];
    }
}

// ---------------------------------------------------------------------------
// Launcher — single stream (round-12 topology; multi-stream overlap measured
// slower twice under graph capture).
// ---------------------------------------------------------------------------
extern "C" void kernel_launch(void* const* d_in, const int* in_sizes, int n_in,
                              void* d_out, int out_size) {
    const float* queries = (const float*)d_in[0];
    const float* weight  = (const float*)d_in[1];
    const float* label   = (const float*)d_in[2];

    float* out = (float*)d_out;
    float* out_scores = out;
    float* out_idx_f  = out + BQ * KK;
    float* out_seqs   = out + 2 * BQ * KK;
    float* out_labels = out + 2 * BQ * KK + (size_t)BQ * KK * DD;

    cudaFuncSetAttribute(gemm_kernel, cudaFuncAttributeMaxDynamicSharedMemorySize, SMEM_TOTAL);

    normalize_kernel<<<BQ, 128>>>(queries);
    transpose_kernel<<<dim3(NN / 64, DD / 64), 256>>>(weight);
    gemm_kernel<<<dim3(BQ / 128, NN / 128), 128, SMEM_TOTAL>>>();
    cand_kernel<<<BQ, 256>>>();
    refine_kernel<<<BQ, 256>>>(label, out_scores, out_idx_f, out_seqs, out_labels);
}